// round 2
// baseline (speedup 1.0000x reference)
#include <cuda_runtime.h>
#include <cuda_fp16.h>
#include <cuda_bf16.h>
#include <cstdint>

// Problem dims
#define B_ 1024
#define C_ 65536
#define D_ 512

// ---------------- scratch (device globals; no runtime allocation) ----------------
__device__ __nv_bfloat16 g_xb[(size_t)B_ * D_];       // 1 MB
__device__ __nv_bfloat16 g_kb[(size_t)C_ * D_];       // 64 MB
__device__ __half        g_ws[(size_t)B_ * C_];       // 128 MB approx ws (fp16)

#define SW128(o)   ((o) ^ (((o) >> 3) & 0x70))

__device__ __forceinline__ uint32_t smem_u32(const void* p) {
    uint32_t a;
    asm("{ .reg .u64 t; cvta.to.shared.u64 t, %1; cvt.u32.u64 %0, t; }" : "=r"(a) : "l"(p));
    return a;
}

__device__ __forceinline__ void ldsm4(uint32_t& r0, uint32_t& r1, uint32_t& r2, uint32_t& r3, uint32_t a) {
    asm volatile("ldmatrix.sync.aligned.m8n8.x4.shared.b16 {%0,%1,%2,%3}, [%4];"
                 : "=r"(r0), "=r"(r1), "=r"(r2), "=r"(r3) : "r"(a));
}

__device__ __forceinline__ void mma16816(float* c, const uint32_t* a, uint32_t b0, uint32_t b1) {
    asm volatile(
        "mma.sync.aligned.m16n8k16.row.col.f32.bf16.bf16.f32 "
        "{%0,%1,%2,%3}, {%4,%5,%6,%7}, {%8,%9}, {%0,%1,%2,%3};"
        : "+f"(c[0]), "+f"(c[1]), "+f"(c[2]), "+f"(c[3])
        : "r"(a[0]), "r"(a[1]), "r"(a[2]), "r"(a[3]), "r"(b0), "r"(b1));
}

// ---------------- kernel 1: fp32 -> bf16 convert ----------------
__global__ void conv_kernel(const float* __restrict__ x, const float* __restrict__ keys) {
    size_t i4 = (size_t)blockIdx.x * blockDim.x + threadIdx.x;
    const size_t NX4 = (size_t)B_ * D_ / 4;   // 131072
    const size_t NK4 = (size_t)C_ * D_ / 4;   // 8388608
    if (i4 < NX4) {
        float4 v = ((const float4*)x)[i4];
        __nv_bfloat162 a = __floats2bfloat162_rn(v.x, v.y);
        __nv_bfloat162 b = __floats2bfloat162_rn(v.z, v.w);
        uint2 o; o.x = *(const unsigned*)&a; o.y = *(const unsigned*)&b;
        ((uint2*)g_xb)[i4] = o;
    } else if (i4 < NX4 + NK4) {
        size_t j = i4 - NX4;
        float4 v = ((const float4*)keys)[j];
        __nv_bfloat162 a = __floats2bfloat162_rn(v.x, v.y);
        __nv_bfloat162 b = __floats2bfloat162_rn(v.z, v.w);
        uint2 o; o.x = *(const unsigned*)&a; o.y = *(const unsigned*)&b;
        ((uint2*)g_kb)[j] = o;
    }
}

// ---------------- kernel 2: bf16 HMMA GEMM (approx ws, fp16 out) ----------------
// CTA tile: M=128 x N=128, K=512 in 8 chunks of 64. 8 warps as 4(M) x 2(N).
// Warp tile 32x64: 2 m16 tiles x 8 n8 tiles, accum 64 fp32 regs.
#define KC 64
#define CHUNK_BYTES 16384            // 128 rows * 128 B (A or B)
#define BUF_BYTES   32768            // A + B per stage
#define SMEM_ALLOC  (2 * BUF_BYTES + 1024)

__device__ __forceinline__ void ldg_chunk(uint4* st, const __nv_bfloat16* Ag,
                                          const __nv_bfloat16* Bg, int k0, int tid) {
    #pragma unroll
    for (int j = 0; j < 4; j++) {
        int u = j * 256 + tid;
        int row = u >> 3, seg = u & 7;
        st[j] = *(const uint4*)(Ag + (size_t)row * D_ + k0 + seg * 8);
    }
    #pragma unroll
    for (int j = 0; j < 4; j++) {
        int u = j * 256 + tid;
        int row = u >> 3, seg = u & 7;
        st[4 + j] = *(const uint4*)(Bg + (size_t)row * D_ + k0 + seg * 8);
    }
}

__device__ __forceinline__ void sts_chunk(char* buf, const uint4* st, int tid) {
    char* sA = buf;
    char* sB = buf + CHUNK_BYTES;
    #pragma unroll
    for (int j = 0; j < 4; j++) {
        int u = j * 256 + tid;
        uint32_t off = (uint32_t)((u >> 3) * 128 + (u & 7) * 16);
        *(uint4*)(sA + SW128(off)) = st[j];
    }
    #pragma unroll
    for (int j = 0; j < 4; j++) {
        int u = j * 256 + tid;
        uint32_t off = (uint32_t)((u >> 3) * 128 + (u & 7) * 16);
        *(uint4*)(sB + SW128(off)) = st[4 + j];
    }
}

__global__ void __launch_bounds__(256) gemm_kernel(const float* __restrict__ logt) {
    extern __shared__ char smraw[];
    uint32_t sbr = smem_u32(smraw);
    uint32_t sb = (sbr + 1023u) & ~1023u;
    char* smem = smraw + (sb - sbr);

    int tid = threadIdx.x;
    int wid = tid >> 5, lane = tid & 31;
    int wm = wid >> 1, wn = wid & 1;
    int mt = blockIdx.x & 7;           // 8 M tiles
    int nt = blockIdx.x >> 3;          // 512 N tiles (consecutive blocks share keys tile)
    int q0 = mt * 128, c0 = nt * 128;

    const __nv_bfloat16* Ag = g_xb + (size_t)q0 * D_;
    const __nv_bfloat16* Bg = g_kb + (size_t)c0 * D_;

    float acc[2][8][4];
    #pragma unroll
    for (int t = 0; t < 2; t++)
        #pragma unroll
        for (int n = 0; n < 8; n++)
            #pragma unroll
            for (int r = 0; r < 4; r++) acc[t][n][r] = 0.f;

    uint4 st[8];
    ldg_chunk(st, Ag, Bg, 0, tid);
    sts_chunk(smem, st, tid);
    __syncthreads();

    // precompute ldmatrix lane address components
    uint32_t smA = sb, smB = sb + CHUNK_BYTES;
    int aRow = wm * 32 + ((lane >> 3) & 1) * 8 + (lane & 7);
    uint32_t aColB = (uint32_t)((lane >> 4) * 16);
    int bm = lane >> 3;
    int bRowIn = (bm >> 1) * 8 + (lane & 7);   // row within n-pair block of 16
    uint32_t bColB = (uint32_t)((bm & 1) * 16);

    #pragma unroll 1
    for (int i = 0; i < 8; i++) {
        if (i < 7) ldg_chunk(st, Ag, Bg, (i + 1) * KC, tid);

        uint32_t bufA = smA + (i & 1) * BUF_BYTES;
        uint32_t bufB = smB + (i & 1) * BUF_BYTES;
        #pragma unroll
        for (int ks = 0; ks < 4; ks++) {
            uint32_t kb = (uint32_t)(ks * 32);
            uint32_t a[2][4];
            #pragma unroll
            for (int t = 0; t < 2; t++) {
                uint32_t off = (uint32_t)((aRow + t * 16) * 128) + kb + aColB;
                ldsm4(a[t][0], a[t][1], a[t][2], a[t][3], bufA + SW128(off));
            }
            uint32_t b[4][4];
            #pragma unroll
            for (int p = 0; p < 4; p++) {
                uint32_t off = (uint32_t)((wn * 64 + p * 16 + bRowIn) * 128) + kb + bColB;
                ldsm4(b[p][0], b[p][1], b[p][2], b[p][3], bufB + SW128(off));
            }
            #pragma unroll
            for (int t = 0; t < 2; t++)
                #pragma unroll
                for (int n = 0; n < 8; n++)
                    mma16816(acc[t][n], a[t], b[n >> 1][(n & 1) * 2], b[n >> 1][(n & 1) * 2 + 1]);
        }
        __syncthreads();
        if (i < 7) {
            sts_chunk(smem + ((i + 1) & 1) * BUF_BYTES, st, tid);
            __syncthreads();
        }
    }

    // epilogue: scale by 1/T, store fp16
    float inv_t = __expf(-logt[0]);
    int g = lane >> 2, tig = lane & 3;
    #pragma unroll
    for (int t = 0; t < 2; t++) {
        #pragma unroll
        for (int h = 0; h < 2; h++) {
            int q = q0 + wm * 32 + t * 16 + g + h * 8;
            __half* dst = g_ws + (size_t)q * C_ + c0 + wn * 64;
            #pragma unroll
            for (int n = 0; n < 8; n++) {
                float v0 = acc[t][n][h * 2 + 0] * inv_t;
                float v1 = acc[t][n][h * 2 + 1] * inv_t;
                *(__half2*)(dst + n * 8 + tig * 2) = __floats2half2_rn(v0, v1);
            }
        }
    }
}

// ---------------- kernel 3: scan max + select + exact fp32 softmax + gather ----------------
#define CAP 4096
__global__ void __launch_bounds__(256) sel_kernel(
    const float* __restrict__ x, const float* __restrict__ keys,
    const float* __restrict__ values, const float* __restrict__ logt,
    float* __restrict__ out)
{
    __shared__ float xs[D_];
    __shared__ int   cidx[CAP];
    __shared__ float cw[CAP];
    __shared__ float red[256];
    __shared__ int   cnt;

    int q = blockIdx.x;
    int tid = threadIdx.x;
    float inv_t = __expf(-logt[0]);

    for (int d = tid; d < D_; d += 256) xs[d] = x[(size_t)q * D_ + d];
    if (tid == 0) cnt = 0;

    // pass 1: row max over fp16 ws
    const uint4* wrow = (const uint4*)(g_ws + (size_t)q * C_);
    const __half2 NEGINF2 = __halves2half2(__ushort_as_half(0xFC00), __ushort_as_half(0xFC00));
    __half2 m2 = NEGINF2;
    #pragma unroll 1
    for (int j = 0; j < 32; j++) {
        union { uint4 v; __half2 h[4]; } u;
        u.v = __ldg(wrow + j * 256 + tid);
        m2 = __hmax2(m2, __hmax2(__hmax2(u.h[0], u.h[1]), __hmax2(u.h[2], u.h[3])));
    }
    float lmax = fmaxf(__low2float(m2), __high2float(m2));
    red[tid] = lmax; __syncthreads();
    for (int s2 = 128; s2; s2 >>= 1) { if (tid < s2) red[tid] = fmaxf(red[tid], red[tid + s2]); __syncthreads(); }
    float mx = red[0];
    __syncthreads();

    // margin: softmax tail (16.5) + fp16 storage err + bf16 GEMM err (in ws units)
    float thr = mx - (16.5f + 0.001f * fabsf(mx) + 0.45f * inv_t);
    __half2 thr2 = __floats2half2_rn(thr, thr);

    // pass 2: select (L2-hot re-read)
    #pragma unroll 1
    for (int j = 0; j < 32; j++) {
        int idx4 = j * 256 + tid;
        union { uint4 v; __half2 h[4]; } u;
        u.v = __ldg(wrow + idx4);
        int cbase = idx4 * 8;
        #pragma unroll
        for (int e = 0; e < 4; e++) {
            unsigned gt = __vcmpgts2(*(unsigned*)&u.h[e] ^ 0u, *(unsigned*)&thr2) ; // unused fast path placeholder
            float f0 = __low2float(u.h[e]);
            float f1 = __high2float(u.h[e]);
            if (f0 > thr) { int p = atomicAdd(&cnt, 1); if (p < CAP) cidx[p] = cbase + e * 2; }
            if (f1 > thr) { int p = atomicAdd(&cnt, 1); if (p < CAP) cidx[p] = cbase + e * 2 + 1; }
            (void)gt;
        }
    }
    __syncthreads();
    int n = min(cnt, CAP);

    // deterministic order (typical n ~ 30)
    if (tid == 0 && n <= 1024) {
        for (int a = 1; a < n; a++) {
            int key = cidx[a]; int bb = a - 1;
            while (bb >= 0 && cidx[bb] > key) { cidx[bb + 1] = cidx[bb]; bb--; }
            cidx[bb + 1] = key;
        }
    }
    __syncthreads();

    // exact fp32 ws for selected candidates (one warp per candidate)
    int w = tid >> 5, lane = tid & 31;
    for (int i = w; i < n; i += 8) {
        const float* kr = keys + (size_t)cidx[i] * D_;
        float s = 0.f;
        #pragma unroll
        for (int kk = 0; kk < 16; kk++) s += xs[lane + kk * 32] * __ldg(kr + lane + kk * 32);
        #pragma unroll
        for (int o = 16; o; o >>= 1) s += __shfl_xor_sync(0xffffffffu, s, o);
        if (lane == 0) cw[i] = s * inv_t;
    }
    __syncthreads();

    // exact max over selected
    float lm = -3.4e38f;
    for (int i = tid; i < n; i += 256) lm = fmaxf(lm, cw[i]);
    red[tid] = lm; __syncthreads();
    for (int s2 = 128; s2; s2 >>= 1) { if (tid < s2) red[tid] = fmaxf(red[tid], red[tid + s2]); __syncthreads(); }
    float m = red[0]; __syncthreads();

    // exp + sum
    float ls = 0.f;
    for (int i = tid; i < n; i += 256) { float e = __expf(cw[i] - m); cw[i] = e; ls += e; }
    red[tid] = ls; __syncthreads();
    for (int s2 = 128; s2; s2 >>= 1) { if (tid < s2) red[tid] += red[tid + s2]; __syncthreads(); }
    float invS = 1.0f / red[0]; __syncthreads();

    // weighted gather of values
    float a0 = 0.f, a1 = 0.f;
    int d0 = tid, d1 = tid + 256;
    for (int i = 0; i < n; i++) {
        float wv = cw[i];
        const float* vr = values + (size_t)cidx[i] * D_;
        a0 += wv * __ldg(vr + d0);
        a1 += wv * __ldg(vr + d1);
    }
    out[(size_t)q * D_ + d0] = a0 * invS;
    out[(size_t)q * D_ + d1] = a1 * invS;
}

// ---------------- launch ----------------
extern "C" void kernel_launch(void* const* d_in, const int* in_sizes, int n_in,
                              void* d_out, int out_size) {
    const float* x      = (const float*)d_in[0];
    const float* keys   = (const float*)d_in[1];
    const float* values = (const float*)d_in[2];
    const float* logt   = (const float*)d_in[3];
    float* out = (float*)d_out;

    static bool attr_done = false;
    if (!attr_done) {
        cudaFuncSetAttribute(gemm_kernel, cudaFuncAttributeMaxDynamicSharedMemorySize, SMEM_ALLOC);
        attr_done = true;
    }

    const int conv_blocks = (int)(((size_t)B_ * D_ / 4 + (size_t)C_ * D_ / 4 + 255) / 256);
    conv_kernel<<<conv_blocks, 256>>>(x, keys);
    gemm_kernel<<<(B_ / 128) * (C_ / 128), 256, SMEM_ALLOC>>>(logt);
    sel_kernel<<<B_, 256>>>(x, keys, values, logt, out);
}